// round 1
// baseline (speedup 1.0000x reference)
#include <cuda_runtime.h>

#define NN 50000
#define NE 500000
#define DIM 160
#define BOND 14

// ---------------- scratch (static device arrays; no allocations) ----------------
__device__ int   g_is64;
__device__ int   g_src[NE];
__device__ int   g_dst[NE];
__device__ float g_P[NN * DIM];           // x @ Wi_x^T + Wi_b
__device__ float g_H0[NE * DIM];
__device__ float g_H[NE * DIM];
__device__ float g_B[NE * DIM];
__device__ float g_M0[NN * DIM];
__device__ float g_M1[NN * DIM];

// ---------------- index dtype detect + convert ----------------
__global__ void k_detect(const void* ei) {
    if (threadIdx.x == 0 && blockIdx.x == 0) {
        const unsigned long long* p = (const unsigned long long*)ei;
        int ok = 1;
        for (int i = 0; i < 1024; i++) {
            if (p[i] >= (unsigned long long)NN) { ok = 0; break; }
        }
        g_is64 = ok;
    }
}

__global__ void k_convert(const void* ei) {
    int i = blockIdx.x * blockDim.x + threadIdx.x;
    if (i >= NE) return;
    if (g_is64) {
        const long long* p = (const long long*)ei;
        g_src[i] = (int)p[i];
        g_dst[i] = (int)p[NE + i];
    } else {
        const int* p = (const int*)ei;
        g_src[i] = p[i];
        g_dst[i] = p[NE + i];
    }
}

// ---------------- generic tiled GEMM: C[M,160] = sum_ph A_ph[M,klen] @ W[:,wk:wk+klen]^T ----------------
// W is row-major [160, ldw]; Ws in smem transposed with stride 161 (conflict-free).
// A tile: 128 rows, stride (klen+4)&~3.  512 threads, micro-tile 4 rows x 10 cols.
// Epilogue options: +bias[h], +AddG[gIdx[row]] (gathered row), relu, store Cout,
// and red.global.add.v4.f32 into MaggRed[dstIdx[row]].
#define GEMM_SMEM ((160*161 + 128*164) * 4)

__global__ __launch_bounds__(512, 1) void k_gemm(
    const float* __restrict__ A0, int lda0, int klen0, int wk0,
    const float* __restrict__ A1, int lda1, int klen1, int wk1,
    int nph, int M,
    const float* __restrict__ W, int ldw,
    const float* __restrict__ bias, int dorelu,
    float* __restrict__ Cout,
    float* __restrict__ MaggRed, const int* __restrict__ dstIdx,
    const float* __restrict__ AddG, const int* __restrict__ gIdx)
{
    extern __shared__ float sm[];
    float* Ws = sm;              // [k*161 + h]
    float* As = sm + 160 * 161;  // [r*astride + k], max astride 164

    const int tid = threadIdx.x;
    const int tx = tid & 15;     // col group: cols tx + j*16
    const int ty = tid >> 4;     // 0..31 -> rows ty*4..ty*4+3
    const int r0 = ty * 4;
    const int row0 = blockIdx.x * 128;

    float acc[4][10];
#pragma unroll
    for (int i = 0; i < 4; i++)
#pragma unroll
        for (int j = 0; j < 10; j++) acc[i][j] = 0.f;

    for (int ph = 0; ph < nph; ph++) {
        const float* A = (ph == 0) ? A0 : A1;
        const int lda  = (ph == 0) ? lda0 : lda1;
        const int klen = (ph == 0) ? klen0 : klen1;
        const int wk   = (ph == 0) ? wk0 : wk1;
        const int astride = (klen + 4) & ~3;

        // load W slice transposed (coalesced gmem, conflict-free smem: stride 161)
        for (int idx = tid; idx < klen * 160; idx += 512) {
            int h = idx / klen, k = idx - h * klen;
            Ws[k * 161 + h] = W[h * ldw + wk + k];
        }
        // load A tile
        if ((klen & 3) == 0 && (lda & 3) == 0) {
            int nq = klen >> 2;
            for (int idx = tid; idx < 128 * nq; idx += 512) {
                int r = idx / nq, q = idx - r * nq;
                int row = row0 + r;
                float4 v = make_float4(0.f, 0.f, 0.f, 0.f);
                if (row < M) v = reinterpret_cast<const float4*>(A + (size_t)row * lda)[q];
                *reinterpret_cast<float4*>(&As[r * astride + q * 4]) = v;
            }
        } else {
            for (int idx = tid; idx < 128 * klen; idx += 512) {
                int r = idx / klen, k = idx - r * klen;
                int row = row0 + r;
                As[r * astride + k] = (row < M) ? A[(size_t)row * lda + k] : 0.f;
            }
        }
        __syncthreads();

#pragma unroll 2
        for (int k = 0; k < klen; k++) {
            float w[10];
#pragma unroll
            for (int j = 0; j < 10; j++) w[j] = Ws[k * 161 + tx + j * 16];
#pragma unroll
            for (int i = 0; i < 4; i++) {
                float a = As[(r0 + i) * astride + k];
#pragma unroll
                for (int j = 0; j < 10; j++) acc[i][j] = fmaf(a, w[j], acc[i][j]);
            }
        }
        __syncthreads();
    }

    // bias, stage to smem (stride 164)
    float bz[10];
    if (bias) {
#pragma unroll
        for (int j = 0; j < 10; j++) bz[j] = bias[tx + j * 16];
    } else {
#pragma unroll
        for (int j = 0; j < 10; j++) bz[j] = 0.f;
    }
#pragma unroll
    for (int i = 0; i < 4; i++)
#pragma unroll
        for (int j = 0; j < 10; j++)
            As[(r0 + i) * 164 + tx + j * 16] = acc[i][j] + bz[j];
    __syncthreads();

    // cooperative vectorized epilogue
    for (int idx = tid; idx < 128 * 40; idx += 512) {
        int r = idx / 40, q = idx - r * 40;
        int row = row0 + r;
        if (row >= M) continue;
        float4 v = *reinterpret_cast<float4*>(&As[r * 164 + q * 4]);
        if (AddG) {
            float4 g = reinterpret_cast<const float4*>(AddG + (size_t)gIdx[row] * DIM)[q];
            v.x += g.x; v.y += g.y; v.z += g.z; v.w += g.w;
        }
        if (dorelu) {
            v.x = fmaxf(v.x, 0.f); v.y = fmaxf(v.y, 0.f);
            v.z = fmaxf(v.z, 0.f); v.w = fmaxf(v.w, 0.f);
        }
        reinterpret_cast<float4*>(Cout + (size_t)row * DIM)[q] = v;
        if (MaggRed) {
            float* p = MaggRed + (size_t)dstIdx[row] * DIM + q * 4;
            asm volatile("red.global.add.v4.f32 [%0], {%1,%2,%3,%4};"
                         :: "l"(p), "f"(v.x), "f"(v.y), "f"(v.z), "f"(v.w) : "memory");
        }
    }
}

// ---------------- edge update: H = relu(H0 + Magg[src] - B[e^1] + b) ----------------
// If Hout != null: store.  If MaggOut != null: red into MaggOut[dst] (final aggregation).
__global__ void k_update(const float* __restrict__ H0, const float* __restrict__ Magg,
                         const float* __restrict__ Bm, const float* __restrict__ bias,
                         float* __restrict__ Hout, float* __restrict__ MaggOut)
{
    int idx = blockIdx.x * blockDim.x + threadIdx.x;
    if (idx >= NE * 40) return;
    int e = idx / 40;
    int q = idx - e * 40;
    float4 v  = reinterpret_cast<const float4*>(H0)[idx];
    float4 m  = reinterpret_cast<const float4*>(Magg + (size_t)g_src[e] * DIM)[q];
    float4 br = reinterpret_cast<const float4*>(Bm + (size_t)(e ^ 1) * DIM)[q];
    float4 b  = reinterpret_cast<const float4*>(bias)[q];
    v.x = fmaxf(v.x + m.x - br.x + b.x, 0.f);
    v.y = fmaxf(v.y + m.y - br.y + b.y, 0.f);
    v.z = fmaxf(v.z + m.z - br.z + b.z, 0.f);
    v.w = fmaxf(v.w + m.w - br.w + b.w, 0.f);
    if (Hout)   reinterpret_cast<float4*>(Hout)[idx] = v;
    if (MaggOut) {
        float* p = MaggOut + (size_t)g_dst[e] * DIM + q * 4;
        asm volatile("red.global.add.v4.f32 [%0], {%1,%2,%3,%4};"
                     :: "l"(p), "f"(v.x), "f"(v.y), "f"(v.z), "f"(v.w) : "memory");
    }
}

// ---------------- where(rowsum==0, x, M) in place on M ----------------
__global__ void k_where(float* __restrict__ M, const float* __restrict__ x)
{
    int gt = blockIdx.x * blockDim.x + threadIdx.x;
    int n = gt >> 5;
    int lane = gt & 31;
    if (n >= NN) return;
    float s = 0.f;
#pragma unroll
    for (int j = 0; j < 5; j++) s += M[n * DIM + lane + j * 32];
#pragma unroll
    for (int o = 16; o; o >>= 1) s += __shfl_xor_sync(0xffffffffu, s, o);
    if (s == 0.f) {
#pragma unroll
        for (int j = 0; j < 5; j++)
            M[n * DIM + lane + j * 32] = x[n * DIM + lane + j * 32];
    }
}

// ---------------- launch ----------------
extern "C" void kernel_launch(void* const* d_in, const int* in_sizes, int n_in,
                              void* d_out, int out_size)
{
    const float* x    = (const float*)d_in[0];
    const float* ea   = (const float*)d_in[1];
    const void*  eidx = d_in[2];
    const float* Wi_w = (const float*)d_in[4];
    const float* Wi_b = (const float*)d_in[5];
    const float* Wh_w = (const float*)d_in[6];
    const float* Wh_b = (const float*)d_in[7];
    const float* Wo_w = (const float*)d_in[8];
    const float* Wo_b = (const float*)d_in[9];
    float* out = (float*)d_out;

    void *pP, *pH0, *pH, *pB, *pM0, *pM1, *pSrc, *pDst;
    cudaGetSymbolAddress(&pP,  g_P);
    cudaGetSymbolAddress(&pH0, g_H0);
    cudaGetSymbolAddress(&pH,  g_H);
    cudaGetSymbolAddress(&pB,  g_B);
    cudaGetSymbolAddress(&pM0, g_M0);
    cudaGetSymbolAddress(&pM1, g_M1);
    cudaGetSymbolAddress(&pSrc, g_src);
    cudaGetSymbolAddress(&pDst, g_dst);

    cudaFuncSetAttribute(k_gemm, cudaFuncAttributeMaxDynamicSharedMemorySize, GEMM_SMEM);

    const int gridE = (NE + 127) / 128;   // 3907
    const int gridN = (NN + 127) / 128;   // 391
    const int gridU = (NE * 40) / 256;    // 78125
    const int gridC = (NE + 255) / 256;   // 1954
    const int gridW = (NN * 32) / 256;    // 6250

    // indices
    k_detect<<<1, 32>>>(eidx);
    k_convert<<<gridC, 256>>>(eidx);

    // P = x @ Wi_x^T + Wi_b   (no relu yet)
    k_gemm<<<gridN, 512, GEMM_SMEM>>>(x, DIM, DIM, 0, nullptr, 0, 0, 0, 1, NN,
                                      Wi_w, DIM + BOND, Wi_b, 0,
                                      (float*)pP, nullptr, nullptr, nullptr, nullptr);

    // H0 = relu(ea @ Wi_e^T + P[src])
    k_gemm<<<gridE, 512, GEMM_SMEM>>>(ea, BOND, BOND, DIM, nullptr, 0, 0, 0, 1, NE,
                                      Wi_w, DIM + BOND, nullptr, 1,
                                      (float*)pH0, nullptr, nullptr,
                                      (const float*)pP, (const int*)pSrc);

    // ---- iteration 1 ----
    cudaMemsetAsync(pM0, 0, (size_t)NN * DIM * sizeof(float));
    k_gemm<<<gridE, 512, GEMM_SMEM>>>((const float*)pH0, DIM, DIM, 0, nullptr, 0, 0, 0, 1, NE,
                                      Wh_w, DIM, nullptr, 0,
                                      (float*)pB, (float*)pM0, (const int*)pDst,
                                      nullptr, nullptr);
    k_update<<<gridU, 256>>>((const float*)pH0, (const float*)pM0, (const float*)pB, Wh_b,
                             (float*)pH, nullptr);

    // ---- iteration 2 (fused final aggregation) ----
    cudaMemsetAsync(pM0, 0, (size_t)NN * DIM * sizeof(float));
    k_gemm<<<gridE, 512, GEMM_SMEM>>>((const float*)pH, DIM, DIM, 0, nullptr, 0, 0, 0, 1, NE,
                                      Wh_w, DIM, nullptr, 0,
                                      (float*)pB, (float*)pM0, (const int*)pDst,
                                      nullptr, nullptr);
    cudaMemsetAsync(pM1, 0, (size_t)NN * DIM * sizeof(float));
    k_update<<<gridU, 256>>>((const float*)pH0, (const float*)pM0, (const float*)pB, Wh_b,
                             nullptr, (float*)pM1);

    // where(rowsum==0, x, M)
    k_where<<<gridW, 256>>>((float*)pM1, x);

    // out = relu([x ; M] @ Wo^T + Wo_b)
    k_gemm<<<gridN, 512, GEMM_SMEM>>>(x, DIM, DIM, 0, (const float*)pM1, DIM, DIM, DIM, 2, NN,
                                      Wo_w, 2 * DIM, Wo_b, 1,
                                      out, nullptr, nullptr, nullptr, nullptr);
}

// round 2
// speedup vs baseline: 1.2312x; 1.2312x over previous
#include <cuda_runtime.h>

#define NN 50000
#define NE 500000
#define DIM 160
#define BOND 14

// ---------------- scratch (static device arrays; no allocations) ----------------
__device__ int   g_is64;
__device__ int   g_src[NE];
__device__ int   g_dst[NE];
__device__ float g_P [NN * DIM];   // x @ Wi_x^T + Wi_b
__device__ float g_H0[NE * DIM];
__device__ float g_B1[NE * DIM];
__device__ float g_B2[NE * DIM];
__device__ float g_M0[NN * DIM];   // seg(B1)
__device__ float g_M0b[NN * DIM];  // seg(B2)
__device__ float g_M1[NN * DIM];   // final seg(H2)

// ---------------- f32x2 helpers (Blackwell FFMA2) ----------------
__device__ __forceinline__ void fma2(unsigned long long& acc,
                                     unsigned long long a, unsigned long long w) {
    asm("fma.rn.f32x2 %0, %1, %2, %0;" : "+l"(acc) : "l"(a), "l"(w));
}
__device__ __forceinline__ unsigned long long splat2(float a) {
    unsigned long long r;
    unsigned int u = __float_as_uint(a);
    asm("mov.b64 %0, {%1, %1};" : "=l"(r) : "r"(u));
    return r;
}
__device__ __forceinline__ float2 unpack2(unsigned long long v) {
    unsigned int lo, hi;
    asm("mov.b64 {%0, %1}, %2;" : "=r"(lo), "=r"(hi) : "l"(v));
    return make_float2(__uint_as_float(lo), __uint_as_float(hi));
}

// ---------------- index dtype detect + convert ----------------
__global__ void k_detect(const void* ei) {
    if (threadIdx.x == 0 && blockIdx.x == 0) {
        const unsigned long long* p = (const unsigned long long*)ei;
        int ok = 1;
        for (int i = 0; i < 1024; i++)
            if (p[i] >= (unsigned long long)NN) { ok = 0; break; }
        g_is64 = ok;
    }
}

__global__ void k_convert(const void* ei) {
    int i = blockIdx.x * blockDim.x + threadIdx.x;
    if (i >= NE) return;
    if (g_is64) {
        const long long* p = (const long long*)ei;
        g_src[i] = (int)p[i];
        g_dst[i] = (int)p[NE + i];
    } else {
        const int* p = (const int*)ei;
        g_src[i] = p[i];
        g_dst[i] = p[NE + i];
    }
}

// ---------------- tiled GEMM: C[M,160] = sum_ph A_ph[M,klen] @ W[:,wk:wk+klen]^T ----------------
// 512 threads, tile 128 rows x 160 cols, micro-tile 4 rows x 5 f32x2 col-pairs.
// Ws in smem transposed, stride 162 (even -> LDS.64, conflict-free).
// As tile stride (klen+4)&~3 (even).
// Fused-A option (fuseH): A row = relu(H0[row] + Magg[src[row]] - Bprev[row^1] + hb)
// Epilogue options: +bias, +AddG[gIdx[row]], relu, store Cout, red.global.add.v4 into MaggRed[dst].
#define WS_STRIDE 162
#define GEMM_SMEM ((160*WS_STRIDE + 128*164) * 4)

__global__ __launch_bounds__(512, 1) void k_gemm(
    const float* __restrict__ A0, int lda0, int klen0, int wk0,
    const float* __restrict__ A1, int lda1, int klen1, int wk1,
    int nph, int M,
    const float* __restrict__ W, int ldw,
    const float* __restrict__ bias, int dorelu,
    float* __restrict__ Cout,
    float* __restrict__ MaggRed, const int* __restrict__ dstIdx,
    const float* __restrict__ AddG, const int* __restrict__ gIdx,
    // fused H-recompute inputs (A := relu(H0 + Mg[src] - Bp[row^1] + hb)), klen=DIM
    int fuseH, const float* __restrict__ fH0, const float* __restrict__ fMg,
    const float* __restrict__ fBp, const float* __restrict__ fhb,
    const int* __restrict__ fsrc)
{
    extern __shared__ float sm[];
    float* Ws = sm;                       // [k*162 + h]
    float* As = sm + 160 * WS_STRIDE;     // [r*astride + k], epilogue stride 164

    const int tid = threadIdx.x;
    const int tx = tid & 15;              // col pairs: 2*tx + 32*j, j=0..4
    const int ty = tid >> 4;              // rows ty*4 .. ty*4+3
    const int r0 = ty * 4;
    const int row0 = blockIdx.x * 128;

    unsigned long long acc[4][5];
#pragma unroll
    for (int i = 0; i < 4; i++)
#pragma unroll
        for (int j = 0; j < 5; j++) acc[i][j] = 0ULL;

    for (int ph = 0; ph < nph; ph++) {
        const float* A = (ph == 0) ? A0 : A1;
        const int lda  = (ph == 0) ? lda0 : lda1;
        const int klen = (ph == 0) ? klen0 : klen1;
        const int wk   = (ph == 0) ? wk0 : wk1;
        const int astride = (klen + 4) & ~3;

        // W slice, transposed into smem
        for (int idx = tid; idx < klen * 160; idx += 512) {
            int h = idx / klen, k = idx - h * klen;
            Ws[k * WS_STRIDE + h] = W[h * ldw + wk + k];
        }

        // A tile
        if (fuseH) {
            // klen == DIM == 160, vector width 4
            for (int idx = tid; idx < 128 * 40; idx += 512) {
                int r = idx / 40, q = idx - r * 40;
                int row = row0 + r;
                float4 v = make_float4(0.f, 0.f, 0.f, 0.f);
                if (row < M) {
                    float4 h0 = reinterpret_cast<const float4*>(fH0 + (size_t)row * DIM)[q];
                    float4 m  = reinterpret_cast<const float4*>(fMg + (size_t)fsrc[row] * DIM)[q];
                    float4 bp = reinterpret_cast<const float4*>(fBp + (size_t)(row ^ 1) * DIM)[q];
                    float4 hb = reinterpret_cast<const float4*>(fhb)[q];
                    v.x = fmaxf(h0.x + m.x - bp.x + hb.x, 0.f);
                    v.y = fmaxf(h0.y + m.y - bp.y + hb.y, 0.f);
                    v.z = fmaxf(h0.z + m.z - bp.z + hb.z, 0.f);
                    v.w = fmaxf(h0.w + m.w - bp.w + hb.w, 0.f);
                }
                *reinterpret_cast<float4*>(&As[r * 164 + q * 4]) = v;
            }
        } else if ((klen & 3) == 0 && (lda & 3) == 0) {
            int nq = klen >> 2;
            for (int idx = tid; idx < 128 * nq; idx += 512) {
                int r = idx / nq, q = idx - r * nq;
                int row = row0 + r;
                float4 v = make_float4(0.f, 0.f, 0.f, 0.f);
                if (row < M) v = reinterpret_cast<const float4*>(A + (size_t)row * lda)[q];
                *reinterpret_cast<float4*>(&As[r * astride + q * 4]) = v;
            }
        } else {
            // klen even (all our shapes): float2 path
            int nq = klen >> 1;
            for (int idx = tid; idx < 128 * nq; idx += 512) {
                int r = idx / nq, q = idx - r * nq;
                int row = row0 + r;
                float2 v = make_float2(0.f, 0.f);
                if (row < M) v = reinterpret_cast<const float2*>(A + (size_t)row * lda)[q];
                *reinterpret_cast<float2*>(&As[r * astride + q * 2]) = v;
            }
        }
        __syncthreads();

#pragma unroll 4
        for (int kk = 0; kk < klen; kk += 2) {
            unsigned long long w0[5], w1[5];
#pragma unroll
            for (int j = 0; j < 5; j++) {
                w0[j] = *(const unsigned long long*)&Ws[kk * WS_STRIDE + 2 * tx + 32 * j];
                w1[j] = *(const unsigned long long*)&Ws[(kk + 1) * WS_STRIDE + 2 * tx + 32 * j];
            }
#pragma unroll
            for (int i = 0; i < 4; i++) {
                float2 a = *(const float2*)&As[(r0 + i) * astride + kk];
                unsigned long long a0 = splat2(a.x);
                unsigned long long a1 = splat2(a.y);
#pragma unroll
                for (int j = 0; j < 5; j++) {
                    fma2(acc[i][j], a0, w0[j]);
                    fma2(acc[i][j], a1, w1[j]);
                }
            }
        }
        __syncthreads();
    }

    // bias + stage to smem (stride 164)
    float2 bz[5];
#pragma unroll
    for (int j = 0; j < 5; j++)
        bz[j] = bias ? *(const float2*)&bias[2 * tx + 32 * j] : make_float2(0.f, 0.f);
#pragma unroll
    for (int i = 0; i < 4; i++)
#pragma unroll
        for (int j = 0; j < 5; j++) {
            float2 v = unpack2(acc[i][j]);
            v.x += bz[j].x; v.y += bz[j].y;
            *(float2*)&As[(r0 + i) * 164 + 2 * tx + 32 * j] = v;
        }
    __syncthreads();

    // cooperative vectorized epilogue
    for (int idx = tid; idx < 128 * 40; idx += 512) {
        int r = idx / 40, q = idx - r * 40;
        int row = row0 + r;
        if (row >= M) continue;
        float4 v = *reinterpret_cast<float4*>(&As[r * 164 + q * 4]);
        if (AddG) {
            float4 g = reinterpret_cast<const float4*>(AddG + (size_t)gIdx[row] * DIM)[q];
            v.x += g.x; v.y += g.y; v.z += g.z; v.w += g.w;
        }
        if (dorelu) {
            v.x = fmaxf(v.x, 0.f); v.y = fmaxf(v.y, 0.f);
            v.z = fmaxf(v.z, 0.f); v.w = fmaxf(v.w, 0.f);
        }
        reinterpret_cast<float4*>(Cout + (size_t)row * DIM)[q] = v;
        if (MaggRed) {
            float* p = MaggRed + (size_t)dstIdx[row] * DIM + q * 4;
            asm volatile("red.global.add.v4.f32 [%0], {%1,%2,%3,%4};"
                         :: "l"(p), "f"(v.x), "f"(v.y), "f"(v.z), "f"(v.w) : "memory");
        }
    }
}

// ---------------- final edge update: H2 = relu(H0 + Magg[src] - B[e^1] + b), red into MaggOut[dst] ----------------
__global__ void k_update(const float* __restrict__ H0, const float* __restrict__ Magg,
                         const float* __restrict__ Bm, const float* __restrict__ bias,
                         float* __restrict__ MaggOut)
{
    int idx = blockIdx.x * blockDim.x + threadIdx.x;
    if (idx >= NE * 40) return;
    int e = idx / 40;
    int q = idx - e * 40;
    float4 v  = reinterpret_cast<const float4*>(H0)[idx];
    float4 m  = reinterpret_cast<const float4*>(Magg + (size_t)g_src[e] * DIM)[q];
    float4 br = reinterpret_cast<const float4*>(Bm + (size_t)(e ^ 1) * DIM)[q];
    float4 b  = reinterpret_cast<const float4*>(bias)[q];
    v.x = fmaxf(v.x + m.x - br.x + b.x, 0.f);
    v.y = fmaxf(v.y + m.y - br.y + b.y, 0.f);
    v.z = fmaxf(v.z + m.z - br.z + b.z, 0.f);
    v.w = fmaxf(v.w + m.w - br.w + b.w, 0.f);
    float* p = MaggOut + (size_t)g_dst[e] * DIM + q * 4;
    asm volatile("red.global.add.v4.f32 [%0], {%1,%2,%3,%4};"
                 :: "l"(p), "f"(v.x), "f"(v.y), "f"(v.z), "f"(v.w) : "memory");
}

// ---------------- where(rowsum==0, x, M) in place on M ----------------
__global__ void k_where(float* __restrict__ M, const float* __restrict__ x)
{
    int gt = blockIdx.x * blockDim.x + threadIdx.x;
    int n = gt >> 5;
    int lane = gt & 31;
    if (n >= NN) return;
    float s = 0.f;
#pragma unroll
    for (int j = 0; j < 5; j++) s += M[n * DIM + lane + j * 32];
#pragma unroll
    for (int o = 16; o; o >>= 1) s += __shfl_xor_sync(0xffffffffu, s, o);
    if (s == 0.f) {
#pragma unroll
        for (int j = 0; j < 5; j++)
            M[n * DIM + lane + j * 32] = x[n * DIM + lane + j * 32];
    }
}

// ---------------- launch ----------------
extern "C" void kernel_launch(void* const* d_in, const int* in_sizes, int n_in,
                              void* d_out, int out_size)
{
    const float* x    = (const float*)d_in[0];
    const float* ea   = (const float*)d_in[1];
    const void*  eidx = d_in[2];
    const float* Wi_w = (const float*)d_in[4];
    const float* Wi_b = (const float*)d_in[5];
    const float* Wh_w = (const float*)d_in[6];
    const float* Wh_b = (const float*)d_in[7];
    const float* Wo_w = (const float*)d_in[8];
    const float* Wo_b = (const float*)d_in[9];
    float* out = (float*)d_out;

    void *pP, *pH0, *pB1, *pB2, *pM0, *pM0b, *pM1, *pSrc, *pDst;
    cudaGetSymbolAddress(&pP,   g_P);
    cudaGetSymbolAddress(&pH0,  g_H0);
    cudaGetSymbolAddress(&pB1,  g_B1);
    cudaGetSymbolAddress(&pB2,  g_B2);
    cudaGetSymbolAddress(&pM0,  g_M0);
    cudaGetSymbolAddress(&pM0b, g_M0b);
    cudaGetSymbolAddress(&pM1,  g_M1);
    cudaGetSymbolAddress(&pSrc, g_src);
    cudaGetSymbolAddress(&pDst, g_dst);

    cudaFuncSetAttribute(k_gemm, cudaFuncAttributeMaxDynamicSharedMemorySize, GEMM_SMEM);

    const int gridE = (NE + 127) / 128;   // 3907
    const int gridN = (NN + 127) / 128;   // 391
    const int gridU = (NE * 40) / 256;    // 78125
    const int gridC = (NE + 255) / 256;   // 1954
    const int gridW = (NN * 32) / 256;    // 6250

    // indices
    k_detect<<<1, 32>>>(eidx);
    k_convert<<<gridC, 256>>>(eidx);

    // P = x @ Wi_x^T + Wi_b
    k_gemm<<<gridN, 512, GEMM_SMEM>>>(x, DIM, DIM, 0, nullptr, 0, 0, 0, 1, NN,
                                      Wi_w, DIM + BOND, Wi_b, 0,
                                      (float*)pP, nullptr, nullptr, nullptr, nullptr,
                                      0, nullptr, nullptr, nullptr, nullptr, nullptr);

    // H0 = relu(ea @ Wi_e^T + P[src])
    k_gemm<<<gridE, 512, GEMM_SMEM>>>(ea, BOND, BOND, DIM, nullptr, 0, 0, 0, 1, NE,
                                      Wi_w, DIM + BOND, nullptr, 1,
                                      (float*)pH0, nullptr, nullptr,
                                      (const float*)pP, (const int*)pSrc,
                                      0, nullptr, nullptr, nullptr, nullptr, nullptr);

    // ---- iteration 1: B1 = H0 @ Wh^T, M0 = seg_dst(B1) ----
    cudaMemsetAsync(pM0, 0, (size_t)NN * DIM * sizeof(float));
    k_gemm<<<gridE, 512, GEMM_SMEM>>>((const float*)pH0, DIM, DIM, 0, nullptr, 0, 0, 0, 1, NE,
                                      Wh_w, DIM, nullptr, 0,
                                      (float*)pB1, (float*)pM0, (const int*)pDst,
                                      nullptr, nullptr,
                                      0, nullptr, nullptr, nullptr, nullptr, nullptr);

    // ---- iteration 2 (fused H1 recompute in A-load): B2 = H1 @ Wh^T, M0b = seg_dst(B2) ----
    cudaMemsetAsync(pM0b, 0, (size_t)NN * DIM * sizeof(float));
    k_gemm<<<gridE, 512, GEMM_SMEM>>>(nullptr, DIM, DIM, 0, nullptr, 0, 0, 0, 1, NE,
                                      Wh_w, DIM, nullptr, 0,
                                      (float*)pB2, (float*)pM0b, (const int*)pDst,
                                      nullptr, nullptr,
                                      1, (const float*)pH0, (const float*)pM0,
                                      (const float*)pB1, Wh_b, (const int*)pSrc);

    // ---- final update: H2 = relu(H0 + M0b[src] - B2[e^1] + b); M1 = seg_dst(H2) ----
    cudaMemsetAsync(pM1, 0, (size_t)NN * DIM * sizeof(float));
    k_update<<<gridU, 256>>>((const float*)pH0, (const float*)pM0b, (const float*)pB2, Wh_b,
                             (float*)pM1);

    // where(rowsum==0, x, M)
    k_where<<<gridW, 256>>>((float*)pM1, x);

    // out = relu([x ; M] @ Wo^T + Wo_b)
    k_gemm<<<gridN, 512, GEMM_SMEM>>>(x, DIM, DIM, 0, (const float*)pM1, DIM, DIM, DIM, 2, NN,
                                      Wo_w, 2 * DIM, Wo_b, 1,
                                      out, nullptr, nullptr, nullptr, nullptr,
                                      0, nullptr, nullptr, nullptr, nullptr, nullptr);
}

// round 3
// speedup vs baseline: 2.0729x; 1.6836x over previous
#include <cuda_runtime.h>
#include <cstdint>

#define NN 50000
#define NE 500000
#define DIM 160
#define BOND 14
#define WS 88   // padded k-stride (bf16 elems) -> conflict-free ldmatrix

// ---------------- scratch ----------------
__device__ int   g_is64;
__device__ int   g_src[NE];
__device__ int   g_dst[NE];
__device__ float g_P [NN * DIM];
__device__ float g_H0[NE * DIM];
__device__ float g_B1[NE * DIM];
__device__ float g_B2[NE * DIM];
__device__ float g_M0[NN * DIM];
__device__ float g_M0b[NN * DIM];
__device__ float g_M1[NN * DIM];
// pre-split weights (bf16 hi/lo), same row strides as fp32 originals
__device__ unsigned short g_Wih[160 * 174], g_Wil[160 * 174];
__device__ unsigned short g_Whh[160 * 160], g_Whl[160 * 160];
__device__ unsigned short g_Woh[160 * 320], g_Wol[160 * 320];

// ---------------- helpers ----------------
__device__ __forceinline__ uint32_t cvta_s(const void* p) {
    uint32_t r;
    asm("{ .reg .u64 t; cvta.to.shared.u64 t, %1; cvt.u32.u64 %0, t; }" : "=r"(r) : "l"(p));
    return r;
}
__device__ __forceinline__ void ldsm4(uint32_t (&r)[4], uint32_t addr) {
    asm volatile("ldmatrix.sync.aligned.m8n8.x4.shared.b16 {%0,%1,%2,%3}, [%4];"
                 : "=r"(r[0]), "=r"(r[1]), "=r"(r[2]), "=r"(r[3]) : "r"(addr));
}
__device__ __forceinline__ void mma16816(float* c, const uint32_t (&a)[4],
                                         uint32_t b0, uint32_t b1) {
    asm volatile("mma.sync.aligned.m16n8k16.row.col.f32.bf16.bf16.f32 "
                 "{%0,%1,%2,%3},{%4,%5,%6,%7},{%8,%9},{%0,%1,%2,%3};"
                 : "+f"(c[0]), "+f"(c[1]), "+f"(c[2]), "+f"(c[3])
                 : "r"(a[0]), "r"(a[1]), "r"(a[2]), "r"(a[3]), "r"(b0), "r"(b1));
}
// split two floats into packed bf16 hi-pair (truncation, exact) and lo-pair
__device__ __forceinline__ void split2(float x, float y, uint32_t& hi2, uint32_t& lo2) {
    uint32_t ux = __float_as_uint(x), uy = __float_as_uint(y);
    hi2 = __byte_perm(ux, uy, 0x7632);
    float lx = x - __uint_as_float(ux & 0xffff0000u);
    float ly = y - __uint_as_float(uy & 0xffff0000u);
    asm("cvt.rn.bf16x2.f32 %0, %1, %2;" : "=r"(lo2) : "f"(ly), "f"(lx));
}

// ---------------- index detect/convert ----------------
__global__ void k_detect(const void* ei) {
    if (threadIdx.x == 0 && blockIdx.x == 0) {
        const unsigned long long* p = (const unsigned long long*)ei;
        int ok = 1;
        for (int i = 0; i < 1024; i++)
            if (p[i] >= (unsigned long long)NN) { ok = 0; break; }
        g_is64 = ok;
    }
}
__global__ void k_convert(const void* ei) {
    int i = blockIdx.x * blockDim.x + threadIdx.x;
    if (i >= NE) return;
    if (g_is64) {
        const long long* p = (const long long*)ei;
        g_src[i] = (int)p[i];
        g_dst[i] = (int)p[NE + i];
    } else {
        const int* p = (const int*)ei;
        g_src[i] = p[i];
        g_dst[i] = p[NE + i];
    }
}

// ---------------- weight split ----------------
__global__ void k_wsplit(const float* __restrict__ w, unsigned short* __restrict__ hi,
                         unsigned short* __restrict__ lo, int n) {
    int i = blockIdx.x * blockDim.x + threadIdx.x;
    if (i >= n) return;
    float f = w[i];
    uint32_t u = __float_as_uint(f);
    hi[i] = (unsigned short)(u >> 16);
    float lf = f - __uint_as_float(u & 0xffff0000u);
    unsigned short ls;
    asm("cvt.rn.bf16.f32 %0, %1;" : "=h"(ls) : "f"(lf));
    lo[i] = ls;
}

// ---------------- tensor-core GEMM ----------------
// C[M,160] = sum_ph A_ph[M,klen] @ W[:, wk:wk+klen]^T  via split-bf16 (3-pass) mma
// 256 thr, tile 128x160; warps 4(m) x 2(n): warp tile 32x80.
#define OFF_WHI 0
#define OFF_WLO (160 * WS * 2)
#define OFF_AHI (2 * 160 * WS * 2)
#define OFF_ALO (2 * 160 * WS * 2 + 128 * WS * 2)
#define MMA_SMEM (2 * 160 * WS * 2 + 2 * 128 * WS * 2)   // 101376 B

__global__ __launch_bounds__(256, 2) void k_mma(
    const float* __restrict__ A0, int lda0, int klen0, int wk0,
    const float* __restrict__ A1, int lda1, int klen1, int wk1,
    int nph, int M,
    const unsigned short* __restrict__ Whi, const unsigned short* __restrict__ Wlo, int ldw,
    const float* __restrict__ bias, int dorelu,
    float* __restrict__ Cout,
    float* __restrict__ MaggRed, const int* __restrict__ dstIdx,
    const float* __restrict__ AddG, const int* __restrict__ gIdx,
    int fuseH, const float* __restrict__ fH0, const float* __restrict__ fMg,
    const float* __restrict__ fBp, const float* __restrict__ fhb,
    const int* __restrict__ fsrc)
{
    extern __shared__ char smem[];
    unsigned short* Whi_s = (unsigned short*)(smem + OFF_WHI);
    unsigned short* Wlo_s = (unsigned short*)(smem + OFF_WLO);
    unsigned short* Ahi_s = (unsigned short*)(smem + OFF_AHI);
    unsigned short* Alo_s = (unsigned short*)(smem + OFF_ALO);
    const uint32_t sbase = cvta_s(smem);

    const int tid = threadIdx.x;
    const int lane = tid & 31, wid = tid >> 5;
    const int warp_m = wid & 3, warp_n = wid >> 2;
    const int m0w = warp_m * 32, n0w = warp_n * 80;
    const int row0 = blockIdx.x * 128;

    // ldmatrix lane addresses (bytes)
    const int arow = (lane & 7) + ((lane >> 3) & 1) * 8;
    const int acol = (lane >> 4) * 8;
    const uint32_t aoff = (uint32_t)((m0w + arow) * WS + acol) * 2;
    const uint32_t aAhi = sbase + OFF_AHI + aoff;
    const uint32_t aAlo = sbase + OFF_ALO + aoff;
    const int brow = (lane & 7) + ((lane >> 4) << 3);
    const int bcol = ((lane >> 3) & 1) * 8;
    const uint32_t boff = (uint32_t)((n0w + brow) * WS + bcol) * 2;
    const uint32_t bWhi = sbase + OFF_WHI + boff;
    const uint32_t bWlo = sbase + OFF_WLO + boff;

    float acc[20][4];
#pragma unroll
    for (int t = 0; t < 20; t++)
#pragma unroll
        for (int j = 0; j < 4; j++) acc[t][j] = 0.f;

    for (int ph = 0; ph < nph; ph++) {
        const float* A = (ph == 0) ? A0 : A1;
        const int lda  = (ph == 0) ? lda0 : lda1;
        const int klen = (ph == 0) ? klen0 : klen1;
        const int wk   = (ph == 0) ? wk0 : wk1;
        const int nch = (klen + 79) / 80;

        for (int c = 0; c < nch; c++) {
            const int k0g = c * 80;
            const int kc = min(80, klen - k0g);
            __syncthreads();

            // ---- load W chunk (bf16 hi/lo) ----
            if (kc == 80) {
                for (int idx = tid; idx < 160 * 40; idx += 256) {
                    int h = idx / 40, q = idx - h * 40;
                    int gi = (h * ldw + wk + k0g) >> 1;
                    *(uint32_t*)&Whi_s[h * WS + q * 2] = ((const uint32_t*)Whi)[gi + q];
                    *(uint32_t*)&Wlo_s[h * WS + q * 2] = ((const uint32_t*)Wlo)[gi + q];
                }
            } else {
                for (int idx = tid; idx < 160 * 80; idx += 256) {
                    int h = idx / 80, kk = idx - h * 80;
                    unsigned short vh = 0, vl = 0;
                    if (kk < kc) {
                        int gi = h * ldw + wk + k0g + kk;
                        vh = Whi[gi]; vl = Wlo[gi];
                    }
                    Whi_s[h * WS + kk] = vh;
                    Wlo_s[h * WS + kk] = vl;
                }
            }

            // ---- load A chunk (fp32 -> split bf16) ----
            if (fuseH) {
                // A := relu(H0 + Mg[src] - Bp[row^1] + hb), klen=160
                for (int idx = tid; idx < 128 * 20; idx += 256) {
                    int r = idx / 20, q = idx - r * 20;
                    int row = row0 + r;
                    float4 v = make_float4(0.f, 0.f, 0.f, 0.f);
                    if (row < M) {
                        int q4 = c * 20 + q;
                        float4 h0 = reinterpret_cast<const float4*>(fH0 + (size_t)row * DIM)[q4];
                        float4 m  = reinterpret_cast<const float4*>(fMg + (size_t)fsrc[row] * DIM)[q4];
                        float4 bp = reinterpret_cast<const float4*>(fBp + (size_t)(row ^ 1) * DIM)[q4];
                        float4 hb = reinterpret_cast<const float4*>(fhb)[q4];
                        v.x = fmaxf(h0.x + m.x - bp.x + hb.x, 0.f);
                        v.y = fmaxf(h0.y + m.y - bp.y + hb.y, 0.f);
                        v.z = fmaxf(h0.z + m.z - bp.z + hb.z, 0.f);
                        v.w = fmaxf(h0.w + m.w - bp.w + hb.w, 0.f);
                    }
                    uint32_t h2a, l2a, h2b, l2b;
                    split2(v.x, v.y, h2a, l2a);
                    split2(v.z, v.w, h2b, l2b);
                    uint32_t* dh = (uint32_t*)&Ahi_s[r * WS + q * 4];
                    uint32_t* dl = (uint32_t*)&Alo_s[r * WS + q * 4];
                    dh[0] = h2a; dh[1] = h2b;
                    dl[0] = l2a; dl[1] = l2b;
                }
            } else if (kc == 80 && (lda & 3) == 0) {
                for (int idx = tid; idx < 128 * 20; idx += 256) {
                    int r = idx / 20, q = idx - r * 20;
                    int row = row0 + r;
                    float4 v = make_float4(0.f, 0.f, 0.f, 0.f);
                    if (row < M)
                        v = *reinterpret_cast<const float4*>(A + (size_t)row * lda + k0g + q * 4);
                    uint32_t h2a, l2a, h2b, l2b;
                    split2(v.x, v.y, h2a, l2a);
                    split2(v.z, v.w, h2b, l2b);
                    uint32_t* dh = (uint32_t*)&Ahi_s[r * WS + q * 4];
                    uint32_t* dl = (uint32_t*)&Alo_s[r * WS + q * 4];
                    dh[0] = h2a; dh[1] = h2b;
                    dl[0] = l2a; dl[1] = l2b;
                }
            } else {
                for (int idx = tid; idx < 128 * 80; idx += 256) {
                    int r = idx / 80, kk = idx - r * 80;
                    int row = row0 + r;
                    float f = 0.f;
                    if (row < M && kk < kc) f = A[(size_t)row * lda + k0g + kk];
                    uint32_t u = __float_as_uint(f);
                    Ahi_s[r * WS + kk] = (unsigned short)(u >> 16);
                    float lf = f - __uint_as_float(u & 0xffff0000u);
                    unsigned short ls;
                    asm("cvt.rn.bf16.f32 %0, %1;" : "=h"(ls) : "f"(lf));
                    Alo_s[r * WS + kk] = ls;
                }
            }
            __syncthreads();

            // ---- mma over k-steps ----
            const int ksteps = (kc + 15) >> 4;
            for (int ks = 0; ks < ksteps; ks++) {
                const uint32_t ko = (uint32_t)ks * 32;
                uint32_t ah0[4], ah1[4], al0[4], al1[4];
                ldsm4(ah0, aAhi + ko);
                ldsm4(ah1, aAhi + ko + 16 * WS * 2);
                ldsm4(al0, aAlo + ko);
                ldsm4(al1, aAlo + ko + 16 * WS * 2);
#pragma unroll
                for (int p = 0; p < 5; p++) {
                    const uint32_t bo = ko + (uint32_t)p * (16 * WS * 2);
                    uint32_t bh[4], bl[4];
                    ldsm4(bh, bWhi + bo);
                    ldsm4(bl, bWlo + bo);
                    mma16816(acc[2 * p],      ah0, bh[0], bh[1]);
                    mma16816(acc[2 * p],      ah0, bl[0], bl[1]);
                    mma16816(acc[2 * p],      al0, bh[0], bh[1]);
                    mma16816(acc[2 * p + 1],  ah0, bh[2], bh[3]);
                    mma16816(acc[2 * p + 1],  ah0, bl[2], bl[3]);
                    mma16816(acc[2 * p + 1],  al0, bh[2], bh[3]);
                    mma16816(acc[10 + 2 * p],     ah1, bh[0], bh[1]);
                    mma16816(acc[10 + 2 * p],     ah1, bl[0], bl[1]);
                    mma16816(acc[10 + 2 * p],     al1, bh[0], bh[1]);
                    mma16816(acc[10 + 2 * p + 1], ah1, bh[2], bh[3]);
                    mma16816(acc[10 + 2 * p + 1], ah1, bl[2], bl[3]);
                    mma16816(acc[10 + 2 * p + 1], al1, bh[2], bh[3]);
                }
            }
        }
    }

    // ---- epilogue: fragments -> gmem directly ----
    float2 bv[10];
#pragma unroll
    for (int nt = 0; nt < 10; nt++)
        bv[nt] = bias ? ((const float2*)bias)[((n0w + nt * 8) >> 1) + (lane & 3)]
                      : make_float2(0.f, 0.f);

#pragma unroll
    for (int mt = 0; mt < 2; mt++) {
        int rbase = row0 + m0w + mt * 16 + (lane >> 2);
#pragma unroll
        for (int half = 0; half < 2; half++) {
            int row = rbase + half * 8;
            if (row >= M) continue;
            const float2* gp = AddG ? (const float2*)(AddG + (size_t)gIdx[row] * DIM) : nullptr;
            float2* cp = (float2*)(Cout + (size_t)row * DIM);
            float* mbase = MaggRed ? (MaggRed + (size_t)dstIdx[row] * DIM) : nullptr;
#pragma unroll
            for (int nt = 0; nt < 10; nt++) {
                int fi = ((n0w + nt * 8) >> 1) + (lane & 3);
                float vx = acc[mt * 10 + nt][half * 2 + 0] + bv[nt].x;
                float vy = acc[mt * 10 + nt][half * 2 + 1] + bv[nt].y;
                if (gp) { float2 g = gp[fi]; vx += g.x; vy += g.y; }
                if (dorelu) { vx = fmaxf(vx, 0.f); vy = fmaxf(vy, 0.f); }
                cp[fi] = make_float2(vx, vy);
                if (mbase) {
                    float* p = mbase + fi * 2;
                    asm volatile("red.global.add.v2.f32 [%0], {%1,%2};"
                                 :: "l"(p), "f"(vx), "f"(vy) : "memory");
                }
            }
        }
    }
}

// ---------------- final edge update ----------------
__global__ void k_update(const float* __restrict__ H0, const float* __restrict__ Magg,
                         const float* __restrict__ Bm, const float* __restrict__ bias,
                         float* __restrict__ MaggOut)
{
    int idx = blockIdx.x * blockDim.x + threadIdx.x;
    if (idx >= NE * 40) return;
    int e = idx / 40;
    int q = idx - e * 40;
    float4 v  = reinterpret_cast<const float4*>(H0)[idx];
    float4 m  = reinterpret_cast<const float4*>(Magg + (size_t)g_src[e] * DIM)[q];
    float4 br = reinterpret_cast<const float4*>(Bm + (size_t)(e ^ 1) * DIM)[q];
    float4 b  = reinterpret_cast<const float4*>(bias)[q];
    v.x = fmaxf(v.x + m.x - br.x + b.x, 0.f);
    v.y = fmaxf(v.y + m.y - br.y + b.y, 0.f);
    v.z = fmaxf(v.z + m.z - br.z + b.z, 0.f);
    v.w = fmaxf(v.w + m.w - br.w + b.w, 0.f);
    float* p = MaggOut + (size_t)g_dst[e] * DIM + q * 4;
    asm volatile("red.global.add.v4.f32 [%0], {%1,%2,%3,%4};"
                 :: "l"(p), "f"(v.x), "f"(v.y), "f"(v.z), "f"(v.w) : "memory");
}

// ---------------- where(rowsum==0, x, M) ----------------
__global__ void k_where(float* __restrict__ M, const float* __restrict__ x)
{
    int gt = blockIdx.x * blockDim.x + threadIdx.x;
    int n = gt >> 5;
    int lane = gt & 31;
    if (n >= NN) return;
    float s = 0.f;
#pragma unroll
    for (int j = 0; j < 5; j++) s += M[n * DIM + lane + j * 32];
#pragma unroll
    for (int o = 16; o; o >>= 1) s += __shfl_xor_sync(0xffffffffu, s, o);
    if (s == 0.f) {
#pragma unroll
        for (int j = 0; j < 5; j++)
            M[n * DIM + lane + j * 32] = x[n * DIM + lane + j * 32];
    }
}

// ---------------- launch ----------------
extern "C" void kernel_launch(void* const* d_in, const int* in_sizes, int n_in,
                              void* d_out, int out_size)
{
    const float* x    = (const float*)d_in[0];
    const float* ea   = (const float*)d_in[1];
    const void*  eidx = d_in[2];
    const float* Wi_w = (const float*)d_in[4];
    const float* Wi_b = (const float*)d_in[5];
    const float* Wh_w = (const float*)d_in[6];
    const float* Wh_b = (const float*)d_in[7];
    const float* Wo_w = (const float*)d_in[8];
    const float* Wo_b = (const float*)d_in[9];
    float* out = (float*)d_out;

    void *pP, *pH0, *pB1, *pB2, *pM0, *pM0b, *pM1, *pSrc, *pDst;
    void *pWih, *pWil, *pWhh, *pWhl, *pWoh, *pWol;
    cudaGetSymbolAddress(&pP,   g_P);
    cudaGetSymbolAddress(&pH0,  g_H0);
    cudaGetSymbolAddress(&pB1,  g_B1);
    cudaGetSymbolAddress(&pB2,  g_B2);
    cudaGetSymbolAddress(&pM0,  g_M0);
    cudaGetSymbolAddress(&pM0b, g_M0b);
    cudaGetSymbolAddress(&pM1,  g_M1);
    cudaGetSymbolAddress(&pSrc, g_src);
    cudaGetSymbolAddress(&pDst, g_dst);
    cudaGetSymbolAddress(&pWih, g_Wih);
    cudaGetSymbolAddress(&pWil, g_Wil);
    cudaGetSymbolAddress(&pWhh, g_Whh);
    cudaGetSymbolAddress(&pWhl, g_Whl);
    cudaGetSymbolAddress(&pWoh, g_Woh);
    cudaGetSymbolAddress(&pWol, g_Wol);

    cudaFuncSetAttribute(k_mma, cudaFuncAttributeMaxDynamicSharedMemorySize, MMA_SMEM);

    const int gridE = (NE + 127) / 128;   // 3907
    const int gridN = (NN + 127) / 128;   // 391
    const int gridU = (NE * 40) / 256;
    const int gridC = (NE + 255) / 256;
    const int gridW = (NN * 32) / 256;

    k_detect<<<1, 32>>>(eidx);
    k_convert<<<gridC, 256>>>(eidx);

    // split weights to bf16 hi/lo
    k_wsplit<<<(160 * 174 + 255) / 256, 256>>>(Wi_w, (unsigned short*)pWih, (unsigned short*)pWil, 160 * 174);
    k_wsplit<<<(160 * 160 + 255) / 256, 256>>>(Wh_w, (unsigned short*)pWhh, (unsigned short*)pWhl, 160 * 160);
    k_wsplit<<<(160 * 320 + 255) / 256, 256>>>(Wo_w, (unsigned short*)pWoh, (unsigned short*)pWol, 160 * 320);

    // P = x @ Wi_x^T + Wi_b
    k_mma<<<gridN, 256, MMA_SMEM>>>(x, DIM, DIM, 0, nullptr, 0, 0, 0, 1, NN,
                                    (const unsigned short*)pWih, (const unsigned short*)pWil, DIM + BOND,
                                    Wi_b, 0, (float*)pP, nullptr, nullptr, nullptr, nullptr,
                                    0, nullptr, nullptr, nullptr, nullptr, nullptr);

    // H0 = relu(ea @ Wi_e^T + P[src])
    k_mma<<<gridE, 256, MMA_SMEM>>>(ea, BOND, BOND, DIM, nullptr, 0, 0, 0, 1, NE,
                                    (const unsigned short*)pWih, (const unsigned short*)pWil, DIM + BOND,
                                    nullptr, 1, (float*)pH0, nullptr, nullptr,
                                    (const float*)pP, (const int*)pSrc,
                                    0, nullptr, nullptr, nullptr, nullptr, nullptr);

    // iter 1: B1 = H0 @ Wh^T; M0 = seg_dst(B1)
    cudaMemsetAsync(pM0, 0, (size_t)NN * DIM * sizeof(float));
    k_mma<<<gridE, 256, MMA_SMEM>>>((const float*)pH0, DIM, DIM, 0, nullptr, 0, 0, 0, 1, NE,
                                    (const unsigned short*)pWhh, (const unsigned short*)pWhl, DIM,
                                    nullptr, 0, (float*)pB1, (float*)pM0, (const int*)pDst,
                                    nullptr, nullptr,
                                    0, nullptr, nullptr, nullptr, nullptr, nullptr);

    // iter 2 (fused H1 recompute): B2 = H1 @ Wh^T; M0b = seg_dst(B2)
    cudaMemsetAsync(pM0b, 0, (size_t)NN * DIM * sizeof(float));
    k_mma<<<gridE, 256, MMA_SMEM>>>(nullptr, DIM, DIM, 0, nullptr, 0, 0, 0, 1, NE,
                                    (const unsigned short*)pWhh, (const unsigned short*)pWhl, DIM,
                                    nullptr, 0, (float*)pB2, (float*)pM0b, (const int*)pDst,
                                    nullptr, nullptr,
                                    1, (const float*)pH0, (const float*)pM0,
                                    (const float*)pB1, Wh_b, (const int*)pSrc);

    // final update: H2 = relu(H0 + M0b[src] - B2[e^1] + b); M1 = seg_dst(H2)
    cudaMemsetAsync(pM1, 0, (size_t)NN * DIM * sizeof(float));
    k_update<<<gridU, 256>>>((const float*)pH0, (const float*)pM0b, (const float*)pB2, Wh_b,
                             (float*)pM1);

    k_where<<<gridW, 256>>>((float*)pM1, x);

    // out = relu([x ; M1] @ Wo^T + Wo_b)
    k_mma<<<gridN, 256, MMA_SMEM>>>(x, DIM, DIM, 0, (const float*)pM1, DIM, DIM, DIM, 2, NN,
                                    (const unsigned short*)pWoh, (const unsigned short*)pWol, 2 * DIM,
                                    Wo_b, 1, out, nullptr, nullptr, nullptr, nullptr,
                                    0, nullptr, nullptr, nullptr, nullptr, nullptr);
}